// round 9
// baseline (speedup 1.0000x reference)
#include <cuda_runtime.h>
#include <cstdint>

#define U_DIM 7
#define V_DIM 7
#define H_DIM 48
#define W_DIM 48
#define C_IN 8
#define OC 8
#define TH 8          // h rows per block tile
#define TCOLS 12      // thread columns, 4 pixels each
#define PPT 4
#define NT_HALF 96    // threads per c-group
#define NTHREADS 192  // two c-groups
#define XSTRIDE 56    // smem row stride (floats)
#define XOFF 4        // data at col w+XOFF; halo zeros at w=-1 / w=48
#define CH_STRIDE (U_DIM * V_DIM * H_DIM * W_DIM)

#define SX_FLOATS (C_IN * (TH + 2) * XSTRIDE)          // 4480 floats (17.5 KB)
#define SMEM_BYTES ((SX_FLOATS + 81 * 64) * 4)         // 38656 B

__device__ __forceinline__ unsigned long long pack2(float v) {
    unsigned long long r;
    asm("mov.b64 %0, {%1, %1};" : "=l"(r) : "f"(v));
    return r;
}
__device__ __forceinline__ void ffma2(unsigned long long& acc,
                                      unsigned long long a,
                                      unsigned long long b) {
    asm("fma.rn.f32x2 %0, %1, %2, %0;" : "+l"(acc) : "l"(a), "l"(b));
}
__device__ __forceinline__ void unpack2(unsigned long long v, float& lo, float& hi) {
    asm("mov.b64 {%0, %1}, %2;" : "=f"(lo), "=f"(hi) : "l"(v));
}

// x:    [2][8][7][7][48][48] fp32
// conv: [8][648]  (oc, tap-major/channel-minor), tap = ((i0*3+i1)*3+i2)*3+i3
// bias: [8]
// out:  [2][8][7][7][48][48]
__global__ __launch_bounds__(NTHREADS, 4) void conv4d_kernel(
    const float* __restrict__ x,
    const float* __restrict__ conv,
    const float* __restrict__ bias,
    float* __restrict__ out)
{
    extern __shared__ float smem[];
    float (*sX)[TH + 2][XSTRIDE] = (float (*)[TH + 2][XSTRIDE])smem;  // [8][10][56]
    float* sWt = smem + SX_FLOATS;                                     // [tap][c][o]

    const int tid = threadIdx.x;
    const int h0  = blockIdx.x * TH;
    const int uv  = blockIdx.y;
    const int u   = uv / V_DIM;
    const int v   = uv % V_DIM;
    const int b   = blockIdx.z;

    // stage weights transposed (covered by first barrier in loop)
    #pragma unroll 4
    for (int idx = tid; idx < 81 * 64; idx += NTHREADS) {
        const int tap = idx >> 6;
        const int c   = (idx >> 3) & 7;
        const int o   = idx & 7;
        sWt[idx] = conv[o * 648 + tap * 8 + c];
    }
    // zero w-halo cols (always globally OOB)
    if (tid < C_IN * (TH + 2)) {
        const int cl = tid / (TH + 2);
        const int r  = tid % (TH + 2);
        sX[cl][r][XOFF - 1]     = 0.0f;
        sX[cl][r][XOFF + W_DIM] = 0.0f;
    }

    // valid (i0,i1) phases
    int ph_off[9], ph_tap[9];
    int nph = 0;
    #pragma unroll
    for (int i0 = 0; i0 < 3; i0++) {
        const int uu = u + i0 - 1;
        if (uu < 0 || uu >= U_DIM) continue;
        #pragma unroll
        for (int i1 = 0; i1 < 3; i1++) {
            const int vv = v + i1 - 1;
            if (vv < 0 || vv >= V_DIM) continue;
            ph_off[nph] = (uu * V_DIM + vv) * (H_DIM * W_DIM);
            ph_tap[nph] = (i0 * 3 + i1) * 9;
            nph++;
        }
    }

    const float* xb = x + (size_t)b * C_IN * CH_STRIDE;

    const int cg    = tid / NT_HALF;        // c-group: 0 -> c 0..3, 1 -> c 4..7
    const int ltid  = tid - cg * NT_HALF;   // 0..95
    const int row   = ltid / TCOLS;         // 0..7
    const int tcol  = ltid % TCOLS;         // 0..11
    const int wbase = tcol * PPT;           // 0,4,...,44

    // cp.async slots: 960 float4 (8ch x 10 rows x 12) over 192 threads -> 5 each
    int pf_goff[5];
    uint32_t pf_sa[5];
    int pf_sz[5];
    #pragma unroll
    for (int k = 0; k < 5; k++) {
        const int idx = tid + k * NTHREADS;
        const int cl  = idx / 120;
        const int rem = idx - cl * 120;
        const int r   = rem / 12;
        const int q   = rem - r * 12;
        const int gh  = h0 + r - 1;
        const bool ok = (gh >= 0) && (gh < H_DIM);
        pf_goff[k] = cl * CH_STRIDE + (ok ? gh : 0) * W_DIM + q * 4;
        pf_sa[k]   = (uint32_t)__cvta_generic_to_shared(&sX[cl][r][XOFF + q * 4]);
        pf_sz[k]   = ok ? 16 : 0;
    }

    // acc[px][op]: pixel px 0..3, oc-pair op 0..3 (lanes oc 2op, 2op+1)
    unsigned long long acc[PPT][4];
    #pragma unroll
    for (int p = 0; p < PPT; p++)
        #pragma unroll
        for (int op = 0; op < 4; op++)
            acc[p][op] = 0ULL;

    for (int p = 0; p < nph; p++) {
        __syncthreads();   // previous compute done before overwrite
        const float* src = xb + ph_off[p];
        #pragma unroll
        for (int k = 0; k < 5; k++)
            asm volatile("cp.async.ca.shared.global [%0], [%1], 16, %2;"
                         :: "r"(pf_sa[k]), "l"(src + pf_goff[k]), "r"(pf_sz[k]));
        asm volatile("cp.async.commit_group;");
        asm volatile("cp.async.wait_group 0;");
        __syncthreads();

        const int tapbase = ph_tap[p];

        #pragma unroll
        for (int ci = 0; ci < 4; ci++) {
            const int cl = cg * 4 + ci;
            #pragma unroll
            for (int i2 = 0; i2 < 3; i2++) {
                // window w-1..w+4 -> smem cols (XOFF-1+wbase)..(XOFF+4+wbase)
                const float* xr = &sX[cl][row + i2][0];
                const float2 xa = *(const float2*)(xr + XOFF - 2 + wbase);  // cols w-2,w-1
                const float4 xm = *(const float4*)(xr + XOFF + wbase);      // w..w+3
                const float2 xc = *(const float2*)(xr + XOFF + 4 + wbase);  // w+4,w+5
                unsigned long long xq[6];
                xq[0] = pack2(xa.y);
                xq[1] = pack2(xm.x);
                xq[2] = pack2(xm.y);
                xq[3] = pack2(xm.z);
                xq[4] = pack2(xm.w);
                xq[5] = pack2(xc.x);

                #pragma unroll
                for (int i3 = 0; i3 < 3; i3++) {
                    const int tap = tapbase + i2 * 3 + i3;
                    const float* wp = &sWt[(tap * 8 + cl) * 8];
                    const ulonglong2 wA = *(const ulonglong2*)wp;        // (o0,o1)(o2,o3)
                    const ulonglong2 wB = *(const ulonglong2*)(wp + 4);  // (o4,o5)(o6,o7)
                    #pragma unroll
                    for (int px = 0; px < PPT; px++) {
                        const unsigned long long xv = xq[i3 + px];
                        ffma2(acc[px][0], xv, wA.x);
                        ffma2(acc[px][1], xv, wA.y);
                        ffma2(acc[px][2], xv, wB.x);
                        ffma2(acc[px][3], xv, wB.y);
                    }
                }
            }
        }
    }

    // cross-group reduction: group 1 dumps partials into smem (overlaid on sX)
    __syncthreads();
    unsigned long long* scratch = (unsigned long long*)smem;   // 96*16 u64 = 12 KB
    if (cg == 1) {
        #pragma unroll
        for (int px = 0; px < PPT; px++)
            #pragma unroll
            for (int op = 0; op < 4; op++)
                scratch[ltid * 16 + px * 4 + op] = acc[px][op];
    }
    __syncthreads();
    if (cg == 0) {
        const int h = h0 + row;
        #pragma unroll
        for (int op = 0; op < 4; op++) {
            const int o0 = 2 * op;
            const float bi0 = __ldg(&bias[o0]);
            const float bi1 = __ldg(&bias[o0 + 1]);
            float4 r0, r1;
            float* pr0 = &r0.x;
            float* pr1 = &r1.x;
            #pragma unroll
            for (int px = 0; px < PPT; px++) {
                float a0, a1, s0, s1;
                unpack2(acc[px][op], a0, a1);
                unpack2(scratch[ltid * 16 + px * 4 + op], s0, s1);
                pr0[px] = a0 + s0 + bi0;
                pr1[px] = a1 + s1 + bi1;
            }
            float* dst0 = &out[((((b * OC + o0) * U_DIM + u) * V_DIM + v) * H_DIM + h) * W_DIM + wbase];
            float* dst1 = &out[((((b * OC + o0 + 1) * U_DIM + u) * V_DIM + v) * H_DIM + h) * W_DIM + wbase];
            *(float4*)dst0 = r0;
            *(float4*)dst1 = r1;
        }
    }
}

extern "C" void kernel_launch(void* const* d_in, const int* in_sizes, int n_in,
                              void* d_out, int out_size)
{
    const float* x    = (const float*)d_in[0];
    const float* conv = (const float*)d_in[1];
    const float* bias = (const float*)d_in[2];
    float* out        = (float*)d_out;

    cudaFuncSetAttribute(conv4d_kernel,
                         cudaFuncAttributeMaxDynamicSharedMemorySize, SMEM_BYTES);

    dim3 grid(H_DIM / TH, U_DIM * V_DIM, 2);   // (6, 49, 2) = 588 blocks
    conv4d_kernel<<<grid, NTHREADS, SMEM_BYTES>>>(x, conv, bias, out);
}

// round 11
// speedup vs baseline: 1.5081x; 1.5081x over previous
#include <cuda_runtime.h>
#include <cuda_bf16.h>
#include <cstdint>

#define PW 50
#define NPIX 2500            // 50*50 padded pixel rows per (b,u,v)
#define PLANE 2304           // 48*48
#define CH_STR 112896        // 7*7*2304
#define RPB 512              // pixel rows per block (8 warps x 64)
#define MARG 64              // sA margin (covers tap shifts +-51)
#define SA_ROWS 640          // MARG + RPB + MARG(64)
#define LO_OFF 10240         // byte offset of lo plane (640*16)
#define NTHREADS 256

__device__ __forceinline__ uint32_t cvt2(float lo, float hi) {   // {lo16,hi16} bf16x2
    uint32_t r;
    asm("cvt.rn.bf16x2.f32 %0, %1, %2;" : "=r"(r) : "f"(hi), "f"(lo));
    return r;
}
__device__ __forceinline__ void ldm4(uint32_t& r0, uint32_t& r1, uint32_t& r2,
                                     uint32_t& r3, uint32_t a) {
    asm volatile("ldmatrix.sync.aligned.m8n8.x4.shared.b16 {%0,%1,%2,%3}, [%4];"
                 : "=r"(r0), "=r"(r1), "=r"(r2), "=r"(r3) : "r"(a));
}
__device__ __forceinline__ void mma16816(float* c, uint32_t a0, uint32_t a1,
                                         uint32_t a2, uint32_t a3,
                                         uint32_t b0, uint32_t b1) {
    asm volatile(
        "mma.sync.aligned.m16n8k16.row.col.f32.bf16.bf16.f32 "
        "{%0,%1,%2,%3}, {%4,%5,%6,%7}, {%8,%9}, {%0,%1,%2,%3};"
        : "+f"(c[0]), "+f"(c[1]), "+f"(c[2]), "+f"(c[3])
        : "r"(a0), "r"(a1), "r"(a2), "r"(a3), "r"(b0), "r"(b1));
}
__device__ __forceinline__ void sts128(uint32_t a, uint32_t r0, uint32_t r1,
                                       uint32_t r2, uint32_t r3) {
    asm volatile("st.shared.v4.b32 [%0], {%1,%2,%3,%4};"
                 :: "r"(a), "r"(r0), "r"(r1), "r"(r2), "r"(r3) : "memory");
}

// x: [2][8][7][7][48][48] f32, conv: [8][648], bias: [8], out: [2][8][7][7][48][48] f32
__global__ __launch_bounds__(NTHREADS) void conv4d_mma(
    const float* __restrict__ x,
    const float* __restrict__ conv,
    const float* __restrict__ bias,
    float* __restrict__ out)
{
    // sA: hi plane rows [0,640) at +0, lo plane at +LO_OFF ; 16B per row (8 bf16 ch)
    __shared__ __align__(16) uint32_t sA4[2 * SA_ROWS * 4];   // 20480 B
    __shared__ uint2 sBF[81 * 32];                            // 20736 B: B frags

    const int tid  = threadIdx.x;
    const int wid  = tid >> 5;
    const int lane = tid & 31;
    const int R0   = blockIdx.x * RPB;
    const int uv   = blockIdx.y;
    const int u    = uv / 7, v = uv % 7;
    const int b    = blockIdx.z;

    const uint32_t sA = (uint32_t)__cvta_generic_to_shared(sA4);

    // ---- precompute B fragments: sBF[tap*32+ln] = {hi pair, lo pair} ----
    // b0 = B[k=(ln%4)*2][n=ln/4], b1 = B[k+1][n]; k = channel, n = oc
    for (int e = tid; e < 81 * 32; e += NTHREADS) {
        const int tap = e >> 5, ln = e & 31;
        const int o = ln >> 2, c0 = (ln & 3) * 2;
        const float w0 = conv[o * 648 + tap * 8 + c0];
        const float w1 = conv[o * 648 + tap * 8 + c0 + 1];
        const uint32_t hi01 = cvt2(w0, w1);
        const float hf0 = __uint_as_float(hi01 << 16);
        const float hf1 = __uint_as_float(hi01 & 0xFFFF0000u);
        sBF[e] = make_uint2(hi01, cvt2(w0 - hf0, w1 - hf1));
    }
    // ---- zero sA (margins/padding rows stay 0 forever) ----
    {
        const uint4 z = make_uint4(0, 0, 0, 0);
        uint4* p = (uint4*)sA4;
        #pragma unroll
        for (int j = tid; j < 2 * SA_ROWS; j += NTHREADS) p[j] = z;
    }

    // ---- valid (i0,i1) phases ----
    int ph_poff[9], ph_tap[9], nph = 0;
    #pragma unroll
    for (int i0 = 0; i0 < 3; i0++) {
        const int uu = u + i0 - 1;
        if (uu < 0 || uu >= 7) continue;
        #pragma unroll
        for (int i1 = 0; i1 < 3; i1++) {
            const int vv = v + i1 - 1;
            if (vv < 0 || vv >= 7) continue;
            ph_poff[nph] = (uu * 7 + vv) * PLANE;
            ph_tap[nph]  = (i0 * 3 + i1) * 9;
            nph++;
        }
    }
    const float* xb = x + (size_t)b * 8 * CH_STR;

    // ---- per-thread transpose rows (phase-independent) ----
    int rw_src[3]; uint32_t rw_sa[3]; bool rw_ok[3];
    #pragma unroll
    for (int k = 0; k < 3; k++) {
        const int j = tid + k * NTHREADS;       // 0..767 (j>=640 invalid)
        const int m = R0 - MARG + j;
        const int mc = m < 0 ? 0 : m;
        const int hp = mc / PW, wp = mc - hp * PW;
        rw_ok[k]  = (j < SA_ROWS) && (m >= 0) && (m < NPIX) &&
                    (hp >= 1) && (hp <= 48) && (wp >= 1) && (wp <= 48);
        rw_src[k] = (hp - 1) * 48 + (wp - 1);
        rw_sa[k]  = sA + j * 16;
    }

    // ---- per-warp ldmatrix base addresses (4 M-tiles of 16 rows) ----
    const int lnrow = lane & 15;                       // row within tile pair
    const uint32_t plane_off = (lane < 16) ? 0u : (uint32_t)LO_OFF;
    uint32_t abase[4];
    #pragma unroll
    for (int t = 0; t < 4; t++)
        abase[t] = sA + plane_off + (MARG + wid * 64 + t * 16 + lnrow) * 16;

    float acc[4][4];
    #pragma unroll
    for (int t = 0; t < 4; t++)
        #pragma unroll
        for (int i = 0; i < 4; i++) acc[t][i] = 0.0f;

    for (int p = 0; p < nph; p++) {
        __syncthreads();   // previous phase's ldmatrix done before overwrite
        const float* src0 = xb + ph_poff[p];
        #pragma unroll
        for (int k = 0; k < 3; k++) {
            if (!rw_ok[k]) continue;
            const float* s = src0 + rw_src[k];
            float vch[8];
            #pragma unroll
            for (int c = 0; c < 8; c++) vch[c] = __ldg(s + c * CH_STR);
            uint32_t hi[4], lo[4];
            #pragma unroll
            for (int q = 0; q < 4; q++) {
                hi[q] = cvt2(vch[2 * q], vch[2 * q + 1]);
                const float hf0 = __uint_as_float(hi[q] << 16);
                const float hf1 = __uint_as_float(hi[q] & 0xFFFF0000u);
                lo[q] = cvt2(vch[2 * q] - hf0, vch[2 * q + 1] - hf1);
            }
            sts128(rw_sa[k], hi[0], hi[1], hi[2], hi[3]);
            sts128(rw_sa[k] + LO_OFF, lo[0], lo[1], lo[2], lo[3]);
        }
        __syncthreads();

        const int tapbase = ph_tap[p];
        #pragma unroll
        for (int t9 = 0; t9 < 9; t9++) {
            const int s16 = ((t9 / 3 - 1) * PW + (t9 % 3 - 1)) * 16;   // byte shift
            const uint2 bf = sBF[(tapbase + t9) * 32 + lane];
            #pragma unroll
            for (int t = 0; t < 4; t++) {
                uint32_t r0, r1, r2, r3;
                ldm4(r0, r1, r2, r3, abase[t] + s16);
                mma16816(acc[t], r0, r1, r2, r3, bf.x, bf.x);   // (xhi+xlo)*Whi
                mma16816(acc[t], r0, r1, r2, r3, bf.y, 0u);     // xhi*Wlo
            }
        }
    }

    // ---- epilogue: D fragment -> gmem ----
    const int oc0 = (lane & 3) * 2;
    const float bi0 = __ldg(&bias[oc0]);
    const float bi1 = __ldg(&bias[oc0 + 1]);
    const size_t obase0 = ((size_t)(b * 8 + oc0) * 49 + uv) * PLANE;
    #pragma unroll
    for (int t = 0; t < 4; t++) {
        const int mrow = R0 + wid * 64 + t * 16 + (lane >> 2);
        #pragma unroll
        for (int half = 0; half < 2; half++) {
            const int m = mrow + half * 8;
            const int hp = m / PW, wp = m - hp * PW;
            if (m < NPIX && hp >= 1 && hp <= 48 && wp >= 1 && wp <= 48) {
                const size_t o = obase0 + (hp - 1) * 48 + (wp - 1);
                out[o]                    = acc[t][half * 2]     + bi0;
                out[o + (size_t)CH_STR]   = acc[t][half * 2 + 1] + bi1;
            }
        }
    }
}

extern "C" void kernel_launch(void* const* d_in, const int* in_sizes, int n_in,
                              void* d_out, int out_size)
{
    const float* x    = (const float*)d_in[0];
    const float* conv = (const float*)d_in[1];
    const float* bias = (const float*)d_in[2];
    float* out        = (float*)d_out;

    dim3 grid(5, 49, 2);   // 490 blocks; 5 x 512 rows cover 2500 padded pixels
    conv4d_mma<<<grid, NTHREADS>>>(x, conv, bias, out);
}